// round 7
// baseline (speedup 1.0000x reference)
#include <cuda_runtime.h>
#include <cuda_bf16.h>
#include <math_constants.h>
#include <stdint.h>

// Problem constants
#define N_TOK 1024
#define HS 2048
#define HT 4096
#define VOCAB 32000

// GEMM tile config
#define BM 128
#define BN 128
#define BK 32
#define SPAD 8
#define SSTRIDE (BK + SPAD)   // 40 bf16 per smem row

// ---------------- device scratch (no allocations allowed) ----------------
__device__ __nv_bfloat16 g_s_logits[(size_t)N_TOK * VOCAB];   // 65.5 MB
__device__ __nv_bfloat16 g_t_logits[(size_t)N_TOK * VOCAB];   // 65.5 MB
__device__ float  g_lse_s[N_TOK];
__device__ float  g_lse_t[N_TOK];
__device__ double g_acc[3];   // [0]=student_kl, [1]=teacher_kl, [2]=hard nll sum
__device__ int    g_is64;     // labels dtype flag

// ---------------- mma helper ----------------
__device__ __forceinline__ void mma16816(float* c, const uint32_t* a, const uint32_t* b) {
    asm volatile(
        "mma.sync.aligned.m16n8k16.row.col.f32.bf16.bf16.f32 "
        "{%0,%1,%2,%3}, {%4,%5,%6,%7}, {%8,%9}, {%0,%1,%2,%3};\n"
        : "+f"(c[0]), "+f"(c[1]), "+f"(c[2]), "+f"(c[3])
        : "r"(a[0]), "r"(a[1]), "r"(a[2]), "r"(a[3]),
          "r"(b[0]), "r"(b[1]));
}

// ---------------- init ----------------
__global__ void init_kernel() {
    g_acc[0] = 0.0; g_acc[1] = 0.0; g_acc[2] = 0.0;
}

// ---------------- label dtype detection ----------------
// Reads ONLY the first 1024 int32 words (4 KB) — in-bounds whether the labels
// buffer is int32[1024] (4 KB) or int64[1024] (8 KB). Interpreting those 4 KB
// as 512 int64 values: for genuine LE int64 labels every hi word is 0 (lab>=0)
// or -1 (lab<0). For int32 labels the "hi" words are random vocab indices, so
// the all-pairs check fails with overwhelming probability.
__global__ void detect_kernel(const int* __restrict__ p) {
    __shared__ int ok;
    if (threadIdx.x == 0) ok = 1;
    __syncthreads();
    int i = threadIdx.x;            // 0..511 -> words (2i, 2i+1), max index 1023
    int lo = p[2 * i];
    int hi = p[2 * i + 1];
    bool good = (hi == 0 && lo >= 0) || (hi == -1 && lo < 0);
    if (!good) ok = 0;
    __syncthreads();
    if (threadIdx.x == 0) g_is64 = ok;
}

// ---------------- bf16 tensor-core GEMM: C[N,V] = A[N,K] * W[V,K]^T + bias ----------------
__global__ __launch_bounds__(256) void gemm_kernel(
    const float* __restrict__ A, const float* __restrict__ W,
    const float* __restrict__ bias, int Kdim, int which_out)
{
    __shared__ __nv_bfloat16 As[BM][SSTRIDE];
    __shared__ __nv_bfloat16 Bs[BN][SSTRIDE];

    __nv_bfloat16* __restrict__ C = which_out ? g_t_logits : g_s_logits;

    const int m0 = blockIdx.x * BM;   // grid.x fastest -> M-blocks sharing a weight tile co-scheduled
    const int n0 = blockIdx.y * BN;
    const int tid = threadIdx.x;
    const int lane = tid & 31;
    const int warp = tid >> 5;
    const int wm = warp & 3;    // 4 warps along M (32 rows each)
    const int wn = warp >> 2;   // 2 warps along N (64 cols each)

    float acc[2][8][4];
#pragma unroll
    for (int mt = 0; mt < 2; mt++)
#pragma unroll
        for (int nt = 0; nt < 8; nt++)
#pragma unroll
            for (int q = 0; q < 4; q++) acc[mt][nt][q] = 0.0f;

    for (int kt = 0; kt < Kdim; kt += BK) {
        // load A tile (128x32 fp32 -> bf16 smem)
#pragma unroll
        for (int i = 0; i < 4; i++) {
            int id = tid + i * 256;          // 0..1023
            int r = id >> 3;                 // row 0..127
            int c4 = id & 7;                 // float4 column 0..7
            float4 v = *(const float4*)(A + (size_t)(m0 + r) * Kdim + kt + c4 * 4);
            __nv_bfloat162 p0 = __floats2bfloat162_rn(v.x, v.y);
            __nv_bfloat162 p1 = __floats2bfloat162_rn(v.z, v.w);
            *(__nv_bfloat162*)&As[r][c4 * 4]     = p0;
            *(__nv_bfloat162*)&As[r][c4 * 4 + 2] = p1;
        }
        // load W tile (128x32 fp32 -> bf16 smem)
#pragma unroll
        for (int i = 0; i < 4; i++) {
            int id = tid + i * 256;
            int r = id >> 3;
            int c4 = id & 7;
            float4 v = *(const float4*)(W + (size_t)(n0 + r) * Kdim + kt + c4 * 4);
            __nv_bfloat162 p0 = __floats2bfloat162_rn(v.x, v.y);
            __nv_bfloat162 p1 = __floats2bfloat162_rn(v.z, v.w);
            *(__nv_bfloat162*)&Bs[r][c4 * 4]     = p0;
            *(__nv_bfloat162*)&Bs[r][c4 * 4 + 2] = p1;
        }
        __syncthreads();

#pragma unroll
        for (int ks = 0; ks < BK; ks += 16) {
            uint32_t af[2][4];
            uint32_t bf[8][2];
#pragma unroll
            for (int mt = 0; mt < 2; mt++) {
                int r = wm * 32 + mt * 16 + (lane >> 2);
                int c = ks + (lane & 3) * 2;
                af[mt][0] = *(const uint32_t*)&As[r][c];
                af[mt][1] = *(const uint32_t*)&As[r + 8][c];
                af[mt][2] = *(const uint32_t*)&As[r][c + 8];
                af[mt][3] = *(const uint32_t*)&As[r + 8][c + 8];
            }
#pragma unroll
            for (int nt = 0; nt < 8; nt++) {
                int n = wn * 64 + nt * 8 + (lane >> 2);
                int c = ks + (lane & 3) * 2;
                bf[nt][0] = *(const uint32_t*)&Bs[n][c];
                bf[nt][1] = *(const uint32_t*)&Bs[n][c + 8];
            }
#pragma unroll
            for (int mt = 0; mt < 2; mt++)
#pragma unroll
                for (int nt = 0; nt < 8; nt++)
                    mma16816(acc[mt][nt], af[mt], bf[nt]);
        }
        __syncthreads();
    }

    // epilogue: add bias, write bf16 logits (paired stores, c is even)
#pragma unroll
    for (int mt = 0; mt < 2; mt++) {
        int r = m0 + wm * 32 + mt * 16 + (lane >> 2);
#pragma unroll
        for (int nt = 0; nt < 8; nt++) {
            int c = n0 + wn * 64 + nt * 8 + (lane & 3) * 2;
            float b0 = bias[c];
            float b1 = bias[c + 1];
            *(__nv_bfloat162*)&C[(size_t)r * VOCAB + c] =
                __floats2bfloat162_rn(acc[mt][nt][0] + b0, acc[mt][nt][1] + b1);
            *(__nv_bfloat162*)&C[(size_t)(r + 8) * VOCAB + c] =
                __floats2bfloat162_rn(acc[mt][nt][2] + b0, acc[mt][nt][3] + b1);
        }
    }
}

// ---------------- per-row logsumexp (student + teacher), vectorized ----------------
#define V8 (VOCAB / 8)    // 4000 uint4-vectors of 8 bf16 per row

__global__ __launch_bounds__(256) void lse_kernel() {
    const int row = blockIdx.x;
    const uint4* __restrict__ s = (const uint4*)(g_s_logits + (size_t)row * VOCAB);
    const uint4* __restrict__ t = (const uint4*)(g_t_logits + (size_t)row * VOCAB);

    float ms = -CUDART_INF_F, ss = 0.0f;
    float mt = -CUDART_INF_F, st = 0.0f;
    for (int j = threadIdx.x; j < V8; j += blockDim.x) {
        uint4 vs = s[j];
        uint4 vt = t[j];
        const __nv_bfloat162* ps = (const __nv_bfloat162*)&vs;
        const __nv_bfloat162* pt = (const __nv_bfloat162*)&vt;
#pragma unroll
        for (int q = 0; q < 4; q++) {
            float2 xs = __bfloat1622float2(ps[q]);
            float2 xt = __bfloat1622float2(pt[q]);
            float x = xs.x;
            if (x > ms) { ss = ss * __expf(ms - x) + 1.0f; ms = x; } else ss += __expf(x - ms);
            x = xs.y;
            if (x > ms) { ss = ss * __expf(ms - x) + 1.0f; ms = x; } else ss += __expf(x - ms);
            x = xt.x;
            if (x > mt) { st = st * __expf(mt - x) + 1.0f; mt = x; } else st += __expf(x - mt);
            x = xt.y;
            if (x > mt) { st = st * __expf(mt - x) + 1.0f; mt = x; } else st += __expf(x - mt);
        }
    }

    __shared__ float shm_s[256], shs_s[256], shm_t[256], shs_t[256];
    int tid = threadIdx.x;
    shm_s[tid] = ms; shs_s[tid] = ss;
    shm_t[tid] = mt; shs_t[tid] = st;
    __syncthreads();
    for (int o = 128; o > 0; o >>= 1) {
        if (tid < o) {
            float m1 = shm_s[tid], m2 = shm_s[tid + o];
            float M = fmaxf(m1, m2);
            shs_s[tid] = shs_s[tid] * __expf(m1 - M) + shs_s[tid + o] * __expf(m2 - M);
            shm_s[tid] = M;
            m1 = shm_t[tid]; m2 = shm_t[tid + o];
            M = fmaxf(m1, m2);
            shs_t[tid] = shs_t[tid] * __expf(m1 - M) + shs_t[tid + o] * __expf(m2 - M);
            shm_t[tid] = M;
        }
        __syncthreads();
    }
    if (tid == 0) {
        g_lse_s[row] = shm_s[0] + __logf(shs_s[0]);
        g_lse_t[row] = shm_t[0] + __logf(shs_t[0]);
    }
}

// ---------------- JSD loss accumulation ----------------
__global__ __launch_bounds__(256) void loss_kernel() {
    const int row = blockIdx.x;
    const float ls = g_lse_s[row];
    const float lt = g_lse_t[row];
    const uint4* __restrict__ s = (const uint4*)(g_s_logits + (size_t)row * VOCAB);
    const uint4* __restrict__ t = (const uint4*)(g_t_logits + (size_t)row * VOCAB);

    float skl = 0.0f, tkl = 0.0f;
    for (int j = threadIdx.x; j < V8; j += blockDim.x) {
        uint4 vs = s[j];
        uint4 vt = t[j];
        const __nv_bfloat162* ps = (const __nv_bfloat162*)&vs;
        const __nv_bfloat162* pt = (const __nv_bfloat162*)&vt;
#pragma unroll
        for (int q = 0; q < 4; q++) {
            float2 xs = __bfloat1622float2(ps[q]);
            float2 xt = __bfloat1622float2(pt[q]);
#pragma unroll
            for (int h = 0; h < 2; h++) {
                float slp = (h ? xs.y : xs.x) - ls;
                float tlp = (h ? xt.y : xt.x) - lt;
                float sp = __expf(slp);
                float tp = __expf(tlp);
                float lm = __logf(0.5f * sp + 0.5f * tp);
                skl += sp * (slp - lm);
                tkl += tp * (tlp - lm);
            }
        }
    }

    __shared__ float sh_s[256], sh_t[256];
    int tid = threadIdx.x;
    sh_s[tid] = skl; sh_t[tid] = tkl;
    __syncthreads();
    for (int o = 128; o > 0; o >>= 1) {
        if (tid < o) {
            sh_s[tid] += sh_s[tid + o];
            sh_t[tid] += sh_t[tid + o];
        }
        __syncthreads();
    }
    if (tid == 0) {
        atomicAdd(&g_acc[0], (double)sh_s[0]);
        atomicAdd(&g_acc[1], (double)sh_t[0]);
    }
}

// ---------------- hard CE (label gather) ----------------
__global__ void hard_kernel(const void* __restrict__ labels_raw) {
    int i = blockIdx.x * blockDim.x + threadIdx.x;
    if (i >= N_TOK) return;
    long long lab;
    if (g_is64) lab = ((const long long*)labels_raw)[i];
    else        lab = (long long)((const int*)labels_raw)[i];
    float v = 0.0f;
    if (lab != -100 && lab >= 0 && lab < VOCAB) {
        float lg = __bfloat162float(g_s_logits[(size_t)i * VOCAB + (size_t)lab]);
        v = g_lse_s[i] - lg;
    }
    atomicAdd(&g_acc[2], (double)v);
}

// ---------------- finalize ----------------
__global__ void finalize_kernel(float* __restrict__ out) {
    double skl = g_acc[0];
    double tkl = g_acc[1];
    double hard = g_acc[2] / (double)N_TOK;
    double jsd = 0.5 * tkl + 0.5 * skl;          // BETA = 0.5
    double soft = jsd / (double)N_TOK;
    out[0] = (float)(0.5 * hard + 0.5 * soft);   // WEIGHT_HARD = WEIGHT_SOFT = 0.5
}

// ---------------- launch ----------------
extern "C" void kernel_launch(void* const* d_in, const int* in_sizes, int n_in,
                              void* d_out, int out_size) {
    const float* SI = (const float*)d_in[0];   // [1024, 2048]
    const float* SW = (const float*)d_in[1];   // [32000, 2048]
    const float* TI = (const float*)d_in[2];   // [1024, 4096]
    const float* TW = (const float*)d_in[3];   // [32000, 4096]
    const void*  LB = d_in[4];                 // [1024] int32 or int64
    const float* sb = (const float*)d_in[5];   // [32000]
    const float* tb = (const float*)d_in[6];   // [32000]

    init_kernel<<<1, 1>>>();
    detect_kernel<<<1, 512>>>((const int*)LB);

    dim3 grid(N_TOK / BM, VOCAB / BN);         // (8, 250): x-fast = M tiles share W tile in L2
    gemm_kernel<<<grid, 256>>>(SI, SW, sb, HS, 0);
    gemm_kernel<<<grid, 256>>>(TI, TW, tb, HT, 1);

    lse_kernel<<<N_TOK, 256>>>();
    loss_kernel<<<N_TOK, 256>>>();
    hard_kernel<<<(N_TOK + 255) / 256, 256>>>(LB);
    finalize_kernel<<<1, 1>>>((float*)d_out);
}

// round 11
// speedup vs baseline: 2.4045x; 2.4045x over previous
#include <cuda_runtime.h>
#include <cuda_bf16.h>
#include <math_constants.h>
#include <stdint.h>

// Problem constants
#define N_TOK 1024
#define HS 2048
#define HT 4096
#define VOCAB 32000

// GEMM tile config: block 256(M) x 128(N), warp 64x64, BK=64 (128B rows, SW128)
#define BM 256
#define BN 128
#define BK 64
#define NTHREADS 256
#define A_STAGE_BYTES (BM * 128)          // 32768
#define B_STAGE_BYTES (BN * 128)          // 16384
#define STAGE_BYTES (A_STAGE_BYTES + B_STAGE_BYTES)   // 49152
#define NSTAGES 3
#define SMEM_DYN (NSTAGES * STAGE_BYTES)  // 147456

// ---------------- device scratch (no allocations allowed) ----------------
__device__ __nv_bfloat16 g_s_logits[(size_t)N_TOK * VOCAB];   // 65.5 MB
__device__ __nv_bfloat16 g_t_logits[(size_t)N_TOK * VOCAB];   // 65.5 MB
__device__ __nv_bfloat16 g_sw_bf[(size_t)VOCAB * HS];         // 131 MB
__device__ __nv_bfloat16 g_tw_bf[(size_t)VOCAB * HT];         // 262 MB
__device__ __nv_bfloat16 g_si_bf[(size_t)N_TOK * HS];         // 4 MB
__device__ __nv_bfloat16 g_ti_bf[(size_t)N_TOK * HT];         // 8 MB
__device__ double g_acc[3];   // [0]=student_kl, [1]=teacher_kl, [2]=hard nll sum
__device__ int    g_is64;

// ---------------- helpers ----------------
__device__ __forceinline__ uint32_t smem_u32(const void* p) {
    uint32_t a;
    asm("{ .reg .u64 t; cvta.to.shared.u64 t, %1; cvt.u32.u64 %0, t; }" : "=r"(a) : "l"(p));
    return a;
}
__device__ __forceinline__ uint32_t packbf(float a, float b) {
    __nv_bfloat162 h = __floats2bfloat162_rn(a, b);
    return *(uint32_t*)&h;
}
__device__ __forceinline__ void mma16816(float* c, const uint32_t* a, const uint32_t* b) {
    asm volatile(
        "mma.sync.aligned.m16n8k16.row.col.f32.bf16.bf16.f32 "
        "{%0,%1,%2,%3}, {%4,%5,%6,%7}, {%8,%9}, {%0,%1,%2,%3};\n"
        : "+f"(c[0]), "+f"(c[1]), "+f"(c[2]), "+f"(c[3])
        : "r"(a[0]), "r"(a[1]), "r"(a[2]), "r"(a[3]),
          "r"(b[0]), "r"(b[1]));
}
__device__ __forceinline__ void ldsm_x4(uint32_t* r, uint32_t addr) {
    asm volatile("ldmatrix.sync.aligned.m8n8.x4.shared.b16 {%0,%1,%2,%3}, [%4];"
        : "=r"(r[0]), "=r"(r[1]), "=r"(r[2]), "=r"(r[3]) : "r"(addr));
}
__device__ __forceinline__ void cp_async16(uint32_t dst, const void* src) {
    asm volatile("cp.async.cg.shared.global [%0], [%1], 16;" :: "r"(dst), "l"(src));
}
#define CP_COMMIT() asm volatile("cp.async.commit_group;" ::: "memory")
#define CP_WAIT2()  asm volatile("cp.async.wait_group 2;" ::: "memory")

// ---------------- init ----------------
__global__ void init_kernel() {
    g_acc[0] = 0.0; g_acc[1] = 0.0; g_acc[2] = 0.0;
}

// ---------------- label dtype detection (reads only first 4 KB — in-bounds for int32[1024]) ----------------
__global__ void detect_kernel(const int* __restrict__ p) {
    __shared__ int ok;
    if (threadIdx.x == 0) ok = 1;
    __syncthreads();
    int i = threadIdx.x;            // 0..511 -> words (2i, 2i+1), max index 1023
    int lo = p[2 * i];
    int hi = p[2 * i + 1];
    bool good = (hi == 0 && lo >= 0) || (hi == -1 && lo < 0);
    if (!good) ok = 0;
    __syncthreads();
    if (threadIdx.x == 0) g_is64 = ok;
}

// ---------------- fp32 -> bf16 conversion pre-pass ----------------
__global__ __launch_bounds__(256) void cvt_kernel(const float* __restrict__ src,
                                                  __nv_bfloat16* __restrict__ dst, int n8) {
    int stride = gridDim.x * blockDim.x;
    for (int i = blockIdx.x * blockDim.x + threadIdx.x; i < n8; i += stride) {
        const float4* s = (const float4*)(src + (size_t)i * 8);
        float4 v0 = s[0], v1 = s[1];
        uint4 u;
        u.x = packbf(v0.x, v0.y); u.y = packbf(v0.z, v0.w);
        u.z = packbf(v1.x, v1.y); u.w = packbf(v1.z, v1.w);
        *(uint4*)(dst + (size_t)i * 8) = u;
    }
}

// ---------------- HMMA GEMM: C[N,V] = A[N,K] * W[V,K]^T + bias, bf16 in, bf16 out ----------------
// grid (4, 500) x-fast; blockIdx.y < 250 -> student, else teacher
__global__ __launch_bounds__(NTHREADS, 1) void gemm_kernel(
    const float* __restrict__ sb, const float* __restrict__ tb)
{
    extern __shared__ char dsm[];
    __shared__ float sbias[BN];

    const int tid = threadIdx.x;
    const int lane = tid & 31;
    const int warp = tid >> 5;
    const int wm = warp >> 1;          // 0..3 (64 rows each)
    const int wn = warp & 1;           // 0..1 (64 cols each)

    const bool isT = blockIdx.y >= 250;
    const __nv_bfloat16* __restrict__ A = isT ? g_ti_bf : g_si_bf;
    const __nv_bfloat16* __restrict__ W = isT ? g_tw_bf : g_sw_bf;
    const float* __restrict__ bs = isT ? tb : sb;
    __nv_bfloat16* __restrict__ C = isT ? g_t_logits : g_s_logits;
    const int Kdim = isT ? HT : HS;
    const int nc = Kdim / BK;          // 32 or 64
    const int m0 = blockIdx.x * BM;
    const int n0 = (isT ? blockIdx.y - 250 : blockIdx.y) * BN;

    if (tid < BN) sbias[tid] = bs[n0 + tid];

    const uint32_t smem = smem_u32(dsm);

    // per-lane ldmatrix swizzled address components (row-invariant parts)
    // A frags: mt = 0..3, row = wm*64 + mt*16 + (lane&15), k-half = lane>>4
    uint32_t a_rowoff[4]; uint32_t a_rx[4];
#pragma unroll
    for (int mt = 0; mt < 4; mt++) {
        int r = wm * 64 + mt * 16 + (lane & 15);
        a_rowoff[mt] = (uint32_t)r * 128;
        a_rx[mt] = (uint32_t)(r & 7);
    }
    const uint32_t a_half = (uint32_t)(lane >> 4);   // adds 1 to the 16B col index
    // B frags: pair = 0..3 (covers n8 tiles 2p, 2p+1)
    // mat = lane>>3: n_off = (mat>>1)*8 + (lane&7), k16 = mat&1
    uint32_t b_rowoff[4]; uint32_t b_rx[4];
    const uint32_t b_k16 = (uint32_t)((lane >> 3) & 1);
#pragma unroll
    for (int p = 0; p < 4; p++) {
        int n = wn * 64 + p * 16 + (((lane >> 3) >> 1) * 8) + (lane & 7);
        b_rowoff[p] = (uint32_t)n * 128;
        b_rx[p] = (uint32_t)(n & 7);
    }

    float acc[4][8][4];
#pragma unroll
    for (int mt = 0; mt < 4; mt++)
#pragma unroll
        for (int nt = 0; nt < 8; nt++)
#pragma unroll
            for (int q = 0; q < 4; q++) acc[mt][nt][q] = 0.0f;

    // ---- async producer: load chunk ch into stage s ----
    auto issue = [&](int s, int ch) {
        const uint32_t Abase = smem + (uint32_t)s * STAGE_BYTES;
        const uint32_t Bbase = Abase + A_STAGE_BYTES;
        const int kt = ch * BK;
        // A: 256 rows x 128B = 2048 x 16B; 8 per thread
#pragma unroll
        for (int it = 0; it < 8; it++) {
            int id = tid + it * 256;
            int row = id >> 3;
            int g = id & 7;
            uint32_t sw = (uint32_t)row * 128 + (uint32_t)((g ^ (row & 7)) << 4);
            cp_async16(Abase + sw, A + (size_t)(m0 + row) * Kdim + kt + g * 8);
        }
        // B: 128 rows x 128B = 1024 x 16B; 4 per thread
#pragma unroll
        for (int it = 0; it < 4; it++) {
            int id = tid + it * 256;
            int row = id >> 3;
            int g = id & 7;
            uint32_t sw = (uint32_t)row * 128 + (uint32_t)((g ^ (row & 7)) << 4);
            cp_async16(Bbase + sw, W + (size_t)(n0 + row) * Kdim + kt + g * 8);
        }
    };

    // prologue: fill 3 stages
    issue(0, 0); CP_COMMIT();
    issue(1, 1); CP_COMMIT();
    issue(2, 2); CP_COMMIT();

    for (int ch = 0; ch < nc; ch++) {
        CP_WAIT2();
        __syncthreads();

        const int s = ch % NSTAGES;
        const uint32_t Abase = smem + (uint32_t)s * STAGE_BYTES;
        const uint32_t Bbase = Abase + A_STAGE_BYTES;

#pragma unroll
        for (int ks = 0; ks < 4; ks++) {
            uint32_t af[4][4], bf[4][4];
            const uint32_t ac16 = (uint32_t)(ks * 2) + a_half;
            const uint32_t bc16 = (uint32_t)(ks * 2) + b_k16;
#pragma unroll
            for (int mt = 0; mt < 4; mt++)
                ldsm_x4(af[mt], Abase + a_rowoff[mt] + ((ac16 ^ a_rx[mt]) << 4));
#pragma unroll
            for (int p = 0; p < 4; p++)
                ldsm_x4(bf[p], Bbase + b_rowoff[p] + ((bc16 ^ b_rx[p]) << 4));
#pragma unroll
            for (int mt = 0; mt < 4; mt++)
#pragma unroll
                for (int p = 0; p < 4; p++) {
                    mma16816(acc[mt][2 * p],     af[mt], &bf[p][0]);
                    mma16816(acc[mt][2 * p + 1], af[mt], &bf[p][2]);
                }
        }
        __syncthreads();
        if (ch + NSTAGES < nc) issue(s, ch + NSTAGES);
        CP_COMMIT();   // always commit to keep group accounting fixed
    }

    // ---- epilogue: bias add, bf16 stores ----
#pragma unroll
    for (int mt = 0; mt < 4; mt++) {
        int r = m0 + wm * 64 + mt * 16 + (lane >> 2);
#pragma unroll
        for (int nt = 0; nt < 8; nt++) {
            int cl = wn * 64 + nt * 8 + (lane & 3) * 2;
            int c = n0 + cl;
            float b0 = sbias[cl];
            float b1 = sbias[cl + 1];
            *(uint32_t*)&C[(size_t)r * VOCAB + c] =
                packbf(acc[mt][nt][0] + b0, acc[mt][nt][1] + b1);
            *(uint32_t*)&C[(size_t)(r + 8) * VOCAB + c] =
                packbf(acc[mt][nt][2] + b0, acc[mt][nt][3] + b1);
        }
    }
}

// ---------------- fused reduce: lse + JSD + hard CE, one block per row ----------------
#define V8 (VOCAB / 8)    // 4000 uint4-vectors of 8 bf16

__global__ __launch_bounds__(256) void reduce_kernel(const void* __restrict__ labels_raw) {
    const int row = blockIdx.x;
    const int tid = threadIdx.x;
    const uint4* __restrict__ s = (const uint4*)(g_s_logits + (size_t)row * VOCAB);
    const uint4* __restrict__ t = (const uint4*)(g_t_logits + (size_t)row * VOCAB);

    // ---- pass 1: online logsumexp for student & teacher ----
    float ms = -CUDART_INF_F, ss = 0.0f;
    float mt = -CUDART_INF_F, st = 0.0f;
    for (int j = tid; j < V8; j += 256) {
        uint4 vs = s[j];
        uint4 vt = t[j];
        const __nv_bfloat162* ps = (const __nv_bfloat162*)&vs;
        const __nv_bfloat162* pt = (const __nv_bfloat162*)&vt;
#pragma unroll
        for (int q = 0; q < 4; q++) {
            float2 xs = __bfloat1622float2(ps[q]);
            float2 xt = __bfloat1622float2(pt[q]);
            float x = xs.x;
            if (x > ms) { ss = ss * __expf(ms - x) + 1.0f; ms = x; } else ss += __expf(x - ms);
            x = xs.y;
            if (x > ms) { ss = ss * __expf(ms - x) + 1.0f; ms = x; } else ss += __expf(x - ms);
            x = xt.x;
            if (x > mt) { st = st * __expf(mt - x) + 1.0f; mt = x; } else st += __expf(x - mt);
            x = xt.y;
            if (x > mt) { st = st * __expf(mt - x) + 1.0f; mt = x; } else st += __expf(x - mt);
        }
    }

    __shared__ float shm_s[256], shs_s[256], shm_t[256], shs_t[256];
    shm_s[tid] = ms; shs_s[tid] = ss;
    shm_t[tid] = mt; shs_t[tid] = st;
    __syncthreads();
    for (int o = 128; o > 0; o >>= 1) {
        if (tid < o) {
            float m1 = shm_s[tid], m2 = shm_s[tid + o];
            float M = fmaxf(m1, m2);
            shs_s[tid] = shs_s[tid] * __expf(m1 - M) + shs_s[tid + o] * __expf(m2 - M);
            shm_s[tid] = M;
            m1 = shm_t[tid]; m2 = shm_t[tid + o];
            M = fmaxf(m1, m2);
            shs_t[tid] = shs_t[tid] * __expf(m1 - M) + shs_t[tid + o] * __expf(m2 - M);
            shm_t[tid] = M;
        }
        __syncthreads();
    }
    __shared__ float bls, blt;
    if (tid == 0) {
        bls = shm_s[0] + __logf(shs_s[0]);
        blt = shm_t[0] + __logf(shs_t[0]);
    }
    __syncthreads();
    const float ls = bls, lt = blt;

    // ---- pass 2: JSD terms (row is L2-resident from pass 1) ----
    float skl = 0.0f, tkl = 0.0f;
    for (int j = tid; j < V8; j += 256) {
        uint4 vs = s[j];
        uint4 vt = t[j];
        const __nv_bfloat162* ps = (const __nv_bfloat162*)&vs;
        const __nv_bfloat162* pt = (const __nv_bfloat162*)&vt;
#pragma unroll
        for (int q = 0; q < 4; q++) {
            float2 xs = __bfloat1622float2(ps[q]);
            float2 xt = __bfloat1622float2(pt[q]);
#pragma unroll
            for (int hh = 0; hh < 2; hh++) {
                float slp = (hh ? xs.y : xs.x) - ls;
                float tlp = (hh ? xt.y : xt.x) - lt;
                float sp = __expf(slp);
                float tp = __expf(tlp);
                float lm = __logf(0.5f * sp + 0.5f * tp);
                skl += sp * (slp - lm);
                tkl += tp * (tlp - lm);
            }
        }
    }
    __shared__ float sh_a[256], sh_b[256];
    sh_a[tid] = skl; sh_b[tid] = tkl;
    __syncthreads();
    for (int o = 128; o > 0; o >>= 1) {
        if (tid < o) {
            sh_a[tid] += sh_a[tid + o];
            sh_b[tid] += sh_b[tid + o];
        }
        __syncthreads();
    }
    if (tid == 0) {
        atomicAdd(&g_acc[0], (double)sh_a[0]);
        atomicAdd(&g_acc[1], (double)sh_b[0]);
        long long lab;
        if (g_is64) lab = ((const long long*)labels_raw)[row];
        else        lab = (long long)((const int*)labels_raw)[row];
        if (lab != -100 && lab >= 0 && lab < VOCAB) {
            float lg = __bfloat162float(g_s_logits[(size_t)row * VOCAB + (size_t)lab]);
            atomicAdd(&g_acc[2], (double)(ls - lg));
        }
    }
}

// ---------------- finalize ----------------
__global__ void finalize_kernel(float* __restrict__ out) {
    double skl = g_acc[0];
    double tkl = g_acc[1];
    double hard = g_acc[2] / (double)N_TOK;
    double jsd = 0.5 * tkl + 0.5 * skl;          // BETA = 0.5
    double soft = jsd / (double)N_TOK;
    out[0] = (float)(0.5 * hard + 0.5 * soft);   // WEIGHT_HARD = WEIGHT_SOFT = 0.5
}

// ---------------- launch ----------------
extern "C" void kernel_launch(void* const* d_in, const int* in_sizes, int n_in,
                              void* d_out, int out_size) {
    const float* SI = (const float*)d_in[0];   // [1024, 2048]
    const float* SW = (const float*)d_in[1];   // [32000, 2048]
    const float* TI = (const float*)d_in[2];   // [1024, 4096]
    const float* TW = (const float*)d_in[3];   // [32000, 4096]
    const void*  LB = d_in[4];                 // [1024] int32 or int64
    const float* sb = (const float*)d_in[5];   // [32000]
    const float* tb = (const float*)d_in[6];   // [32000]

    static int smem_set = 0;
    cudaFuncSetAttribute(gemm_kernel, cudaFuncAttributeMaxDynamicSharedMemorySize, SMEM_DYN);
    (void)smem_set;

    init_kernel<<<1, 1>>>();
    detect_kernel<<<1, 512>>>((const int*)LB);

    // bf16 pre-conversion
    __nv_bfloat16 *swp, *twp, *sip, *tip;
    cudaGetSymbolAddress((void**)&swp, g_sw_bf);
    cudaGetSymbolAddress((void**)&twp, g_tw_bf);
    cudaGetSymbolAddress((void**)&sip, g_si_bf);
    cudaGetSymbolAddress((void**)&tip, g_ti_bf);
    cvt_kernel<<<1184, 256>>>(SW, swp, VOCAB * HS / 8);
    cvt_kernel<<<1184, 256>>>(TW, twp, VOCAB * HT / 8);
    cvt_kernel<<<296, 256>>>(SI, sip, N_TOK * HS / 8);
    cvt_kernel<<<296, 256>>>(TI, tip, N_TOK * HT / 8);

    // fused student+teacher GEMM
    gemm_kernel<<<dim3(N_TOK / BM, 2 * (VOCAB / BN)), NTHREADS, SMEM_DYN>>>(sb, tb);

    reduce_kernel<<<N_TOK, 256>>>(LB);
    finalize_kernel<<<1, 1>>>((float*)d_out);
}